// round 3
// baseline (speedup 1.0000x reference)
#include <cuda_runtime.h>
#include <cuda_bf16.h>
#include <cstdint>

#define T_DIM 256
#define B_DIM 256
#define H_DIM 512
#define K_DIM 64
#define M_DIM (T_DIM * B_DIM)

// Scratch (device globals; no allocations anywhere)
__device__ float g_em[(size_t)M_DIM * K_DIM];   // emissions [T,B,K] f32
__device__ float g_diff[B_DIM];                 // per-batch forward - gold

__device__ __forceinline__ uint32_t f2bf2(float lo, float hi) {
    uint32_t r;
    asm("cvt.rn.bf16x2.f32 %0, %1, %2;" : "=r"(r) : "f"(hi), "f"(lo));
    return r;
}

// ---------------------------------------------------------------------------
// Kernel 1: emissions GEMM  em[m,k] = sum_h hid[m,h] * W[k,h] + b[k]
// W staged per-block into SMEM as u64 = (bf16x2 lo-k, bf16x2 hi-k) with a
// bank-exact XOR swizzle -> 8 conflict-free LDS.64 per thread per k-iter.
// A loads double-buffered. bf16 mma.sync m16n8k16, fp32 accum.
// ---------------------------------------------------------------------------
extern __shared__ unsigned long long sB[];   // 8192 u64 = 64 KB dynamic

__global__ __launch_bounds__(256, 3) void emis_gemm(const float* __restrict__ hid,
                                                    const float* __restrict__ W,
                                                    const float* __restrict__ bias) {
    int tid = threadIdx.x;

    // Stage W: u64[n][kk][tg] = ( W2[n][8kk+tg] , W2[n][8kk+tg+4] )
    // smem index: (kk*4+tg)*64 + (n ^ sw(tg)),  sw(tg) = ((tg&1)<<3)|((tg>>1)<<2)
    for (int i = tid; i < (K_DIM * H_DIM) / 4; i += 256) {
        int n  = i >> 7;
        int r  = i & 127;
        int kk = r >> 2;
        int tg = r & 3;
        const float2* src = (const float2*)(W + n * H_DIM + kk * 16 + tg * 2);
        float2 lo = src[0];
        float2 hi = src[4];     // +8 floats
        uint32_t wl = f2bf2(lo.x, lo.y);
        uint32_t wh = f2bf2(hi.x, hi.y);
        unsigned long long u;
        asm("mov.b64 %0, {%1,%2};" : "=l"(u) : "r"(wl), "r"(wh));
        int sw = ((tg & 1) << 3) | ((tg >> 1) << 2);
        sB[(kk * 4 + tg) * 64 + (n ^ sw)] = u;
    }
    __syncthreads();

    int warp = tid >> 5;
    int lane = tid & 31;
    int g  = lane >> 2;   // 0..7
    int tg = lane & 3;    // 0..3
    int swb = ((tg & 1) << 3) | ((tg >> 1) << 2);
    int row0 = blockIdx.x * 128 + warp * 16;

    const float* a0p = hid + (size_t)(row0 + g) * H_DIM + tg * 2;
    const float* a1p = hid + (size_t)(row0 + g + 8) * H_DIM + tg * 2;

    float acc[8][4];
#pragma unroll
    for (int nt = 0; nt < 8; nt++)
#pragma unroll
        for (int q = 0; q < 4; q++) acc[nt][q] = 0.f;

    // prime A double-buffer
    float2 v0 = *(const float2*)(a0p);
    float2 v1 = *(const float2*)(a1p);
    float2 v2 = *(const float2*)(a0p + 8);
    float2 v3 = *(const float2*)(a1p + 8);

#pragma unroll 4
    for (int kk = 0; kk < 32; kk++) {
        uint32_t a0 = f2bf2(v0.x, v0.y);
        uint32_t a1 = f2bf2(v1.x, v1.y);
        uint32_t a2 = f2bf2(v2.x, v2.y);
        uint32_t a3 = f2bf2(v3.x, v3.y);
        if (kk < 31) {
            int k0 = (kk + 1) * 16;
            v0 = *(const float2*)(a0p + k0);
            v1 = *(const float2*)(a1p + k0);
            v2 = *(const float2*)(a0p + k0 + 8);
            v3 = *(const float2*)(a1p + k0 + 8);
        }
        int rowoff = (kk * 4 + tg) << 6;
#pragma unroll
        for (int nt = 0; nt < 8; nt++) {
            uint2 bb = *(const uint2*)(sB + rowoff + (((nt << 3) + g) ^ swb));
            asm volatile(
                "mma.sync.aligned.m16n8k16.row.col.f32.bf16.bf16.f32 "
                "{%0,%1,%2,%3}, {%4,%5,%6,%7}, {%8,%9}, {%0,%1,%2,%3};"
                : "+f"(acc[nt][0]), "+f"(acc[nt][1]), "+f"(acc[nt][2]), "+f"(acc[nt][3])
                : "r"(a0), "r"(a1), "r"(a2), "r"(a3), "r"(bb.x), "r"(bb.y));
        }
    }

    int r0 = row0 + g, r1 = row0 + g + 8;
#pragma unroll
    for (int nt = 0; nt < 8; nt++) {
        int c = nt * 8 + tg * 2;
        float b0v = bias[c], b1v = bias[c + 1];
        float2 o;
        o.x = acc[nt][0] + b0v; o.y = acc[nt][1] + b1v;
        *(float2*)(g_em + (size_t)r0 * K_DIM + c) = o;
        o.x = acc[nt][2] + b0v; o.y = acc[nt][3] + b1v;
        *(float2*)(g_em + (size_t)r1 * K_DIM + c) = o;
    }
}

// ---------------------------------------------------------------------------
// Kernel 2: CRF forward DP + gold score. 2 batches/block, 64 threads each
// (named barriers). Log-free recurrence on unnormalized vector u:
//   s_j = sum_i expT[j,i] * u_i
//   u'_j = s_j * exp(em'_j - em'_0) * inv            (inv = 1/s0 one step back)
//   C   += em'_0 - log(inv_prev)                     (thread 0 only)
// exp(em diff) precomputed one step early (off critical path); per-step
// critical path = bar + LDS + 32 FMA2 + 1 FMUL + STS.
// ---------------------------------------------------------------------------
#define FMA2(acc, a, b) \
    asm("fma.rn.f32x2 %0, %1, %2, %3;" : "=l"(acc) : "l"(a), "l"(b), "l"(acc))

__global__ __launch_bounds__(128) void crf_dp(const int* __restrict__ lens,
                                              const int* __restrict__ tags,
                                              const float* __restrict__ trans,
                                              const float* __restrict__ begin,
                                              const float* __restrict__ endt) {
    int tid  = threadIdx.x;
    int gid  = tid >> 6;          // batch group within block
    int j    = tid & 63;
    int lane = tid & 31;
    int wing = (tid >> 5) & 1;
    int b    = blockIdx.x * 2 + gid;
    int len  = lens[b];
    int barid = gid + 1;

    __shared__ __align__(16) float sm_u[2][2][64];
    __shared__ float sm_inv[2][2];
    __shared__ float sm_g[2][2];

#define GBAR() asm volatile("bar.sync %0, 64;" :: "r"(barid) : "memory")

    // ---- gold path score (parallel segment sum over t) ----
    float gpart = 0.f;
    for (int t = j; t < len; t += 64) {
        int tag = tags[t * B_DIM + b];
        float inc;
        if (t == 0) inc = begin[tag];
        else        inc = trans[tag * K_DIM + tags[(t - 1) * B_DIM + b]];
        inc += g_em[((size_t)t * B_DIM + b) * K_DIM + tag];
        gpart += inc;
    }
#pragma unroll
    for (int o = 16; o; o >>= 1) gpart += __shfl_down_sync(0xffffffffu, gpart, o);
    if (lane == 0) sm_g[gid][wing] = gpart;
    GBAR();
    float goldv = 0.f;
    if (j == 0)
        goldv = sm_g[gid][0] + sm_g[gid][1] + endt[tags[(len - 1) * B_DIM + b]];

    // ---- exp(transition) row j, packed f32x2 ----
    unsigned long long eT2[32];
    {
        const float4* tr4 = (const float4*)(trans + j * K_DIM);
#pragma unroll
        for (int q = 0; q < 16; q++) {
            float4 v = tr4[q];
            float e0 = __expf(v.x), e1 = __expf(v.y);
            float e2 = __expf(v.z), e3 = __expf(v.w);
            asm("mov.b64 %0, {%1,%2};" : "=l"(eT2[2*q])   : "f"(e0), "f"(e1));
            asm("mov.b64 %0, {%1,%2};" : "=l"(eT2[2*q+1]) : "f"(e2), "f"(e3));
        }
    }

    // ---- init (t = 0): u0_j = exp(alpha_j(0) - alpha_0(0)), C = alpha_0(0) ----
    float a00 = begin[0] + g_em[(size_t)b * K_DIM];            // broadcast loads
    float u0  = __expf(begin[j] + g_em[(size_t)b * K_DIM + j] - a00);
    float C = a00;                                             // thread 0 only
    sm_u[gid][0][j] = u0;
    if (j == 0) sm_inv[gid][0] = 1.f;
    float u_reg = u0;

    // em pipeline: x_cur = exp(em[t+1][j]-em[t+1][0]); em_a = em[t+2] regs
    float x_cur = 1.f, em0_cur = 0.f, em_aj = 0.f, em_a0 = 0.f;
    if (len > 1) {
        size_t base = ((size_t)B_DIM + b) * K_DIM;
        float ej = g_em[base + j], e0 = g_em[base];
        x_cur = __expf(ej - e0); em0_cur = e0;
    }
    if (len > 2) {
        size_t base = ((size_t)2 * B_DIM + b) * K_DIM;
        em_aj = g_em[base + j]; em_a0 = g_em[base];
    }
    GBAR();

    // ---- serial DP: len-1 steps, ONE named barrier each ----
    for (int t = 0; t < len - 1; t++) {
        int buf = t & 1, nbuf = buf ^ 1;

        float inv = sm_inv[gid][buf];
        const ulonglong2* pp = (const ulonglong2*)sm_u[gid][buf];
        unsigned long long acc0 = 0, acc1 = 0, acc2 = 0, acc3 = 0;
#pragma unroll
        for (int q = 0; q < 16; q += 2) {
            ulonglong2 va = pp[q];
            ulonglong2 vb = pp[q + 1];
            FMA2(acc0, va.x, eT2[2*q]);
            FMA2(acc1, va.y, eT2[2*q+1]);
            FMA2(acc2, vb.x, eT2[2*q+2]);
            FMA2(acc3, vb.y, eT2[2*q+3]);
        }
        float s;
        {
            float l0, h0, l1, h1, l2, h2, l3, h3;
            asm("mov.b64 {%0,%1}, %2;" : "=f"(l0), "=f"(h0) : "l"(acc0));
            asm("mov.b64 {%0,%1}, %2;" : "=f"(l1), "=f"(h1) : "l"(acc1));
            asm("mov.b64 {%0,%1}, %2;" : "=f"(l2), "=f"(h2) : "l"(acc2));
            asm("mov.b64 {%0,%1}, %2;" : "=f"(l3), "=f"(h3) : "l"(acc3));
            s = ((l0 + h0) + (l1 + h1)) + ((l2 + h2) + (l3 + h3));
        }
        float un = s * (x_cur * inv);
        sm_u[gid][nbuf][j] = un;
        if (j == 0) {
            float invn;
            asm("rcp.approx.f32 %0, %1;" : "=f"(invn) : "f"(s));
            sm_inv[gid][nbuf] = invn;
            C += em0_cur - __logf(inv);   // uses the ACTUAL inv applied to u
        }

        // rotate em pipeline (off critical path)
        float x_next = __expf(em_aj - em_a0);
        float em0_next = em_a0;
        if (t + 3 < len) {
            size_t base = ((size_t)(t + 3) * B_DIM + b) * K_DIM;
            em_aj = g_em[base + j]; em_a0 = g_em[base];
        }
        u_reg = un; x_cur = x_next; em0_cur = em0_next;
        GBAR();
    }

    // ---- forward = C + log(sum_j u_j * exp(end_j)) ----
    float val = u_reg * __expf(endt[j]);
#pragma unroll
    for (int o = 16; o; o >>= 1) val += __shfl_down_sync(0xffffffffu, val, o);
    if (lane == 0) sm_g[gid][wing] = val;
    GBAR();
    if (j == 0) {
        float fwd = C + __logf(sm_g[gid][0] + sm_g[gid][1]);
        g_diff[b] = fwd - goldv;
    }
#undef GBAR
}

// ---------------------------------------------------------------------------
// Kernel 3: deterministic final reduction
// ---------------------------------------------------------------------------
__global__ void final_reduce(float* __restrict__ out) {
    __shared__ float s[256];
    int t = threadIdx.x;
    s[t] = g_diff[t];
    __syncthreads();
    for (int k = 128; k > 0; k >>= 1) {
        if (t < k) s[t] += s[t + k];
        __syncthreads();
    }
    if (t == 0) out[0] = s[0];
}

// ---------------------------------------------------------------------------
extern "C" void kernel_launch(void* const* d_in, const int* in_sizes, int n_in,
                              void* d_out, int out_size) {
    const float* hiddens = (const float*)d_in[0];   // [T,B,H] f32
    const int*   lens    = (const int*)d_in[1];     // [B]
    const int*   tags    = (const int*)d_in[2];     // [T,B]
    const float* W       = (const float*)d_in[3];   // [K,H]
    const float* bias    = (const float*)d_in[4];   // [K]
    const float* begin   = (const float*)d_in[5];   // [K]
    const float* trans   = (const float*)d_in[6];   // [K,K]
    const float* endt    = (const float*)d_in[7];   // [K]
    float* out = (float*)d_out;

    cudaFuncSetAttribute(emis_gemm, cudaFuncAttributeMaxDynamicSharedMemorySize, 65536);

    emis_gemm<<<M_DIM / 128, 256, 65536>>>(hiddens, W, bias);
    crf_dp<<<B_DIM / 2, 128>>>(lens, tags, trans, begin, endt);
    final_reduce<<<1, 256>>>(out);
}